// round 8
// baseline (speedup 1.0000x reference)
#include <cuda_runtime.h>
#include <cstdint>
#include <cstddef>

// Problem constants:
//   x: [B=64, Cin=64, T=1, K=4096] f32
//   w: [Cin=64, Cout=64, F=4] f32   (w[i][o][f] = w[i*256 + (o*4+f)])
//   idx: [L=16384] i32
//   out[b,o,l] = res[b, o*4+f, k] with f=idx[l]>>12, k=idx[l]&4095
#define B_    64
#define CIN   64
#define K_    4096
#define COUT  64
#define F_    4
#define L_    16384
#define M_    256            // COUT * F_

// 268 MB scratch: res[b][m][k]  (== plane-contiguous [b][o][f*4096+k])
__device__ float g_res[(size_t)B_ * M_ * K_];

// ---------------------------------------------------------------------------
// tf32 helpers + mma
// ---------------------------------------------------------------------------
__device__ __forceinline__ unsigned tf32_of(float v) {
    unsigned r;
    asm("cvt.rna.tf32.f32 %0, %1;" : "=r"(r) : "f"(v));
    return r;
}
__device__ __forceinline__ unsigned tf32_lo(float v) {
    float hi = __uint_as_float(tf32_of(v));
    return tf32_of(v - hi);
}
__device__ __forceinline__ void mma_tf32(float* d, const unsigned* a, const unsigned* b) {
    asm("mma.sync.aligned.m16n8k8.row.col.f32.tf32.tf32.f32 "
        "{%0,%1,%2,%3}, {%4,%5,%6,%7}, {%8,%9}, {%0,%1,%2,%3};"
        : "+f"(d[0]), "+f"(d[1]), "+f"(d[2]), "+f"(d[3])
        : "r"(a[0]), "r"(a[1]), "r"(a[2]), "r"(a[3]), "r"(b[0]), "r"(b[1]));
}

// ---------------------------------------------------------------------------
// Kernel 1: split-tf32 GEMM  res[b, m, k] = sum_i w[i,m] * x[b,i,k]
//   3xTF32: acc = Wh*Xh + Wl*Xh + Wh*Xl   (augmented reduction K=192)
//   Block: 256 thr, tile M=128 x N=128k, 2 CTAs/SM. Warp tile m32 x n64.
//   A smem: fragment-packed [pass(h/l)][ichunk(2)][s(4)][mf(8)][lane(32)][4]
//   B smem: fragment-packed [s(4)][nf(16)][lane(32)][2], restaged 4x
//     (chunks: Xh rows 0-31, Xh rows 32-63, Xl rows 0-31, Xl rows 32-63;
//      Xh chunks feed A passes {Wh, Wl}; Xl chunks feed {Wh}.)
// ---------------------------------------------------------------------------
#define GT 256
#define A_FLOATS 16384          // 2*2*4*8*32*4
#define B_FLOATS 4096           // 4*16*32*2
#define GSMEM ((A_FLOATS + B_FLOATS) * 4)   // 80 KB -> 2 CTAs/SM

__global__ void __launch_bounds__(GT, 2)
gemm_kernel(const float* __restrict__ x, const float* __restrict__ w) {
    extern __shared__ float sm[];
    float* As = sm;
    float* Bs = sm + A_FLOATS;

    const int t  = threadIdx.x;
    const int k0 = blockIdx.x * 128;
    const int m0 = blockIdx.y * 128;
    const int b  = blockIdx.z;

    // ---- stage A (both tf32 passes), fragment-packed ----
    // float4-slot q: lane=q&31, mf=(q>>5)&7, s=(q>>8)&3, ch=(q>>10)&1, pass=q>>11
#pragma unroll
    for (int r = 0; r < 16; r++) {
        int q = t + GT * r;                 // 0..4095
        int lane = q & 31, mf = (q >> 5) & 7, s = (q >> 8) & 3;
        int ch = (q >> 10) & 1, pass = q >> 11;
        int g = lane >> 2, c = lane & 3;
        int i0 = ch * 32 + s * 8 + c;
        int mr = m0 + mf * 16 + g;
        float v0 = w[i0 * M_ + mr];
        float v1 = w[i0 * M_ + mr + 8];
        float v2 = w[(i0 + 4) * M_ + mr];
        float v3 = w[(i0 + 4) * M_ + mr + 8];
        float4 st;
        if (pass == 0) {
            st.x = __uint_as_float(tf32_of(v0));
            st.y = __uint_as_float(tf32_of(v1));
            st.z = __uint_as_float(tf32_of(v2));
            st.w = __uint_as_float(tf32_of(v3));
        } else {
            st.x = __uint_as_float(tf32_lo(v0));
            st.y = __uint_as_float(tf32_lo(v1));
            st.z = __uint_as_float(tf32_lo(v2));
            st.w = __uint_as_float(tf32_lo(v3));
        }
        *(float4*)(As + q * 4) = st;
    }

    const int lane = t & 31;
    const int wq   = t >> 5;       // 0..7
    const int mw   = wq >> 1;      // 0..3  (m32 tile)
    const int nw   = wq & 1;       // 0..1  (n64 tile)

    float acc[2][8][4];
#pragma unroll
    for (int m = 0; m < 2; m++)
#pragma unroll
        for (int n = 0; n < 8; n++)
#pragma unroll
            for (int e = 0; e < 4; e++) acc[m][n][e] = 0.0f;

    const float4* x4 = (const float4*)x;

    for (int bc = 0; bc < 4; bc++) {
        const int ch = bc & 1;      // i-rows 0-31 / 32-63
        const int xp = bc >> 1;     // 0: Xh, 1: Xl
        __syncthreads();
        // ---- stage B chunk: 32 i-rows x 128 k, fragment-packed ----
        {
            const int irow0 = ch * 32;
#pragma unroll
            for (int r = 0; r < 4; r++) {
                int q = t + GT * r;            // 0..1023 float4s
                int il = q >> 5, kq = q & 31;
                float4 v = x4[(((size_t)(b * CIN + irow0 + il)) << 10) + (k0 >> 2) + kq];
                float vv[4] = {v.x, v.y, v.z, v.w};
                int s = il >> 3, tg = il & 3, h = (il >> 2) & 1;
#pragma unroll
                for (int e = 0; e < 4; e++) {
                    int kle = kq * 4 + e;
                    int nf = kle >> 3, g = kle & 7;
                    unsigned u = (xp == 0) ? tf32_of(vv[e]) : tf32_lo(vv[e]);
                    Bs[((((s * 16 + nf) * 32) + (g * 4 + tg)) << 1) + h] = __uint_as_float(u);
                }
            }
        }
        __syncthreads();

        const int nap = (xp == 0) ? 2 : 1;     // Xh: Wh+Wl passes; Xl: Wh only
        for (int ap = 0; ap < nap; ap++) {
            const float* Ab = As + (ap * 2 + ch) * 4096;
#pragma unroll
            for (int s = 0; s < 4; s++) {
                unsigned af[2][4];
#pragma unroll
                for (int m = 0; m < 2; m++) {
                    float4 av = *(const float4*)(Ab + s * 1024 + (mw * 2 + m) * 128 + lane * 4);
                    af[m][0] = __float_as_uint(av.x);
                    af[m][1] = __float_as_uint(av.y);
                    af[m][2] = __float_as_uint(av.z);
                    af[m][3] = __float_as_uint(av.w);
                }
                unsigned bf[8][2];
#pragma unroll
                for (int n = 0; n < 8; n++) {
                    float2 bv = *(const float2*)(Bs + (((s * 16 + (nw * 8 + n)) * 32 + lane) << 1));
                    bf[n][0] = __float_as_uint(bv.x);
                    bf[n][1] = __float_as_uint(bv.y);
                }
#pragma unroll
                for (int m = 0; m < 2; m++)
#pragma unroll
                    for (int n = 0; n < 8; n++)
                        mma_tf32(acc[m][n], af[m], bf[n]);
            }
        }
    }

    // ---- epilogue: STG.64, 32B-sector coalesced ----
    const int g = lane >> 2, tg = lane & 3;
#pragma unroll
    for (int m = 0; m < 2; m++) {
        int mr = m0 + (mw * 2 + m) * 16 + g;
        float* dstm = g_res + (((size_t)b * M_ + mr) << 12);
#pragma unroll
        for (int n = 0; n < 8; n++) {
            int kc = k0 + (nw * 8 + n) * 8 + tg * 2;
            *(float2*)(dstm + kc)           = make_float2(acc[m][n][0], acc[m][n][1]);
            *(float2*)(dstm + (8 << 12) + kc) = make_float2(acc[m][n][2], acc[m][n][3]);
        }
    }
}

// ---------------------------------------------------------------------------
// Kernel 2: per-plane gather. block = (b,o) plane (64 KB), 512 threads.
// ---------------------------------------------------------------------------
#define HT 512

__global__ void __launch_bounds__(HT, 2)
gather_kernel(const int* __restrict__ idx, float* __restrict__ out) {
    extern __shared__ float plane[];   // 16384 floats = 64 KB
    const int t = threadIdx.x;
    const int p = blockIdx.x;          // b*64 + o

    const float4* src4 = (const float4*)(g_res + (size_t)p * L_);
    float4*       pl4  = (float4*)plane;
#pragma unroll
    for (int r = 0; r < 8; r++)
        pl4[t + HT * r] = __ldcs(src4 + t + HT * r);
    __syncthreads();

    const int4* idx4 = (const int4*)idx;
    float4*     dst4 = (float4*)(out + (size_t)p * L_);
#pragma unroll 4
    for (int r = 0; r < 8; r++) {
        int4 id = idx4[t + HT * r];
        float4 v;
        v.x = plane[id.x];
        v.y = plane[id.y];
        v.z = plane[id.z];
        v.w = plane[id.w];
        __stcs(dst4 + t + HT * r, v);
    }
}

// ---------------------------------------------------------------------------
extern "C" void kernel_launch(void* const* d_in, const int* in_sizes, int n_in,
                              void* d_out, int out_size) {
    const float* x   = (const float*)d_in[0];
    const float* w   = (const float*)d_in[1];
    const int*   idx = (const int*)d_in[2];
    float*       out = (float*)d_out;
    (void)in_sizes; (void)n_in; (void)out_size;

    cudaFuncSetAttribute(gemm_kernel,
                         cudaFuncAttributeMaxDynamicSharedMemorySize, GSMEM);
    cudaFuncSetAttribute(gather_kernel,
                         cudaFuncAttributeMaxDynamicSharedMemorySize, L_ * 4);

    dim3 ggrid(K_ / 128, 2, B_);                 // 32 x 2 x 64 = 4096 blocks
    gemm_kernel<<<ggrid, GT, GSMEM>>>(x, w);

    gather_kernel<<<B_ * COUT, HT, L_ * 4>>>(idx, out);
}

// round 11
// speedup vs baseline: 2.2489x; 2.2489x over previous
#include <cuda_runtime.h>
#include <cuda_bf16.h>
#include <cstdint>
#include <cstddef>

// Problem constants:
//   x: [B=64, Cin=64, T=1, K=4096] f32
//   w: [Cin=64, Cout=64, F=4] f32   (w[i][m], m = o*4+f, M=256)
//   idx: [L=16384] i32
//   out[b,o,l] = res[b, m=(o*4+f), k],  f=idx[l]>>12, k=idx[l]&4095
#define B_    64
#define CIN   64
#define K_    4096
#define COUT  64
#define L_    16384
#define M_    256

// 268 MB scratch: res[b][m][k]
__device__ float g_res[(size_t)B_ * M_ * K_];

// ---------------------------------------------------------------------------
// bf16 helpers
// ---------------------------------------------------------------------------
__device__ __forceinline__ void bf16_split2(float v0, float v1,
                                            uint32_t& hi, uint32_t& lo) {
    __nv_bfloat16 h0 = __float2bfloat16(v0);
    __nv_bfloat16 h1 = __float2bfloat16(v1);
    float r0 = v0 - __bfloat162float(h0);
    float r1 = v1 - __bfloat162float(h1);
    hi = (uint32_t)__bfloat16_as_ushort(h0) |
         ((uint32_t)__bfloat16_as_ushort(h1) << 16);
    lo = (uint32_t)__bfloat16_as_ushort(__float2bfloat16(r0)) |
         ((uint32_t)__bfloat16_as_ushort(__float2bfloat16(r1)) << 16);
}

// mma.sync m16n8k16 row.col bf16 -> f32  (baseline PTX, valid on sm_103)
__device__ __forceinline__ void mma_bf16(float* d, const uint32_t* a,
                                         const uint32_t* b) {
    asm volatile(
        "mma.sync.aligned.m16n8k16.row.col.f32.bf16.bf16.f32 "
        "{%0,%1,%2,%3}, {%4,%5,%6,%7}, {%8,%9}, {%0,%1,%2,%3};"
        : "+f"(d[0]), "+f"(d[1]), "+f"(d[2]), "+f"(d[3])
        : "r"(a[0]), "r"(a[1]), "r"(a[2]), "r"(a[3]), "r"(b[0]), "r"(b[1]));
}

// ---------------------------------------------------------------------------
// Kernel 1: split-bf16 HMMA GEMM  res[b,m,k] = sum_i w[i,m] * x[b,i,k]
//   3-term split: Wh*Xh + Wh*Xl + Wl*Xh  (f32 accum), rel err ~2^-16.
//   Block: 256 thr, tile M=128 x N=128, K=64 staged once. 2 CTAs/SM.
//   Warp tile m32 x n64 (4 m-warps x 2 n-warps).
//   Smem rows of 36 b32 words (32 data + 4 pad): bank = (4*row + col) % 32
//   -> fragment LDS.32 (lanes g=0..7, t=0..3) conflict-free.
// ---------------------------------------------------------------------------
#define ROWW 36
#define AH_OFF 0
#define AL_OFF (128 * ROWW)
#define BH_OFF (2 * 128 * ROWW)
#define BL_OFF (3 * 128 * ROWW)
#define GSMEM  (4 * 128 * ROWW * 4)     // 73728 B -> 2 CTAs/SM

__global__ void __launch_bounds__(256, 2)
gemm_kernel(const float* __restrict__ x, const float* __restrict__ w) {
    extern __shared__ uint32_t sm32[];

    const int t  = threadIdx.x;
    const int k0 = blockIdx.x * 128;
    const int m0 = blockIdx.y * 128;
    const int b  = blockIdx.z;

    // ---- stage: threads 0-127 -> A rows (m), threads 128-255 -> B rows (n) ----
    {
        const int r   = t & 127;
        const bool isB = t >= 128;
        const float* src;
        size_t stride;
        if (isB) { src = x + (((size_t)b * CIN) << 12) + k0 + r; stride = K_; }
        else     { src = w + m0 + r;                              stride = M_; }
        uint32_t* dh = sm32 + (isB ? BH_OFF : AH_OFF) + r * ROWW;
        uint32_t* dl = sm32 + (isB ? BL_OFF : AL_OFF) + r * ROWW;
        const int ph = (r >> 3) & 3;     // stagger: conflict-free STS
#pragma unroll 8
        for (int q = 0; q < 32; q++) {
            int ip = (q + ph) & 31;      // i-pair index
            float v0 = src[(size_t)(2 * ip)     * stride];
            float v1 = src[(size_t)(2 * ip + 1) * stride];
            uint32_t hi, lo;
            bf16_split2(v0, v1, hi, lo);
            dh[ip] = hi;
            dl[ip] = lo;
        }
    }
    __syncthreads();

    // ---- compute ----
    const int lane = t & 31;
    const int wq   = t >> 5;
    const int wm   = wq & 3;            // 0..3 : m-warp (32 rows each)
    const int wn   = wq >> 2;           // 0..1 : n-warp (64 cols each)
    const int g    = lane >> 2;
    const int tg   = lane & 3;

    float acc[2][8][4];
#pragma unroll
    for (int mt = 0; mt < 2; mt++)
#pragma unroll
        for (int j = 0; j < 8; j++)
#pragma unroll
            for (int e = 0; e < 4; e++) acc[mt][j][e] = 0.0f;

    const int aR0 = (32 * wm + g) * ROWW;        // a-row base (mt=0), +16*ROWW mt=1
    const int bR0 = (64 * wn + g) * ROWW;        // b-row base (j=0), +8*ROWW per j

#pragma unroll
    for (int ks = 0; ks < 4; ks++) {
        const int c0 = 8 * ks + tg;              // frag word col (a0/a1/b0)
        const int c4 = c0 + 4;                   // (a2/a3/b1)

        // Ah fragments (2 m-tiles)
        uint32_t ah[2][4];
#pragma unroll
        for (int mt = 0; mt < 2; mt++) {
            int rb = aR0 + AH_OFF + mt * 16 * ROWW;
            ah[mt][0] = sm32[rb + c0];
            ah[mt][1] = sm32[rb + 8 * ROWW + c0];
            ah[mt][2] = sm32[rb + c4];
            ah[mt][3] = sm32[rb + 8 * ROWW + c4];
        }
        // Bh fragments, kept for the Al pass
        uint32_t bh[8][2];
#pragma unroll
        for (int j = 0; j < 8; j++) {
            int rb = bR0 + BH_OFF + j * 8 * ROWW;
            bh[j][0] = sm32[rb + c0];
            bh[j][1] = sm32[rb + c4];
        }
        // term 1: Ah * Bh
#pragma unroll
        for (int j = 0; j < 8; j++) {
            mma_bf16(acc[0][j], ah[0], bh[j]);
            mma_bf16(acc[1][j], ah[1], bh[j]);
        }
        // term 2: Ah * Bl (streamed)
#pragma unroll
        for (int j = 0; j < 8; j++) {
            int rb = bR0 + BL_OFF + j * 8 * ROWW;
            uint32_t bl[2] = { sm32[rb + c0], sm32[rb + c4] };
            mma_bf16(acc[0][j], ah[0], bl);
            mma_bf16(acc[1][j], ah[1], bl);
        }
        // term 3: Al * Bh (reuse kept bh)
        uint32_t al[2][4];
#pragma unroll
        for (int mt = 0; mt < 2; mt++) {
            int rb = aR0 + AL_OFF + mt * 16 * ROWW;
            al[mt][0] = sm32[rb + c0];
            al[mt][1] = sm32[rb + 8 * ROWW + c0];
            al[mt][2] = sm32[rb + c4];
            al[mt][3] = sm32[rb + 8 * ROWW + c4];
        }
#pragma unroll
        for (int j = 0; j < 8; j++) {
            mma_bf16(acc[0][j], al[0], bh[j]);
            mma_bf16(acc[1][j], al[1], bh[j]);
        }
    }

    // ---- epilogue: direct STG.64, 32B sectors fully covered ----
#pragma unroll
    for (int mt = 0; mt < 2; mt++) {
        int row0 = m0 + 32 * wm + 16 * mt + g;
        float* d0 = g_res + (((size_t)b * M_ + row0) << 12) + k0 + 64 * wn + 2 * tg;
        float* d1 = d0 + ((size_t)8 << 12);
#pragma unroll
        for (int j = 0; j < 8; j++) {
            *(float2*)(d0 + 8 * j) = make_float2(acc[mt][j][0], acc[mt][j][1]);
            *(float2*)(d1 + 8 * j) = make_float2(acc[mt][j][2], acc[mt][j][3]);
        }
    }
}

// ---------------------------------------------------------------------------
// Kernel 2: per-plane gather. block = (b,o) plane (64 KB), 512 threads.
// ---------------------------------------------------------------------------
#define HT 512

__global__ void __launch_bounds__(HT, 2)
gather_kernel(const int* __restrict__ idx, float* __restrict__ out) {
    extern __shared__ float plane[];   // 16384 floats = 64 KB
    const int t = threadIdx.x;
    const int p = blockIdx.x;          // b*64 + o

    const float4* src4 = (const float4*)(g_res + (size_t)p * L_);
    float4*       pl4  = (float4*)plane;
#pragma unroll
    for (int r = 0; r < 8; r++)
        pl4[t + HT * r] = __ldcs(src4 + t + HT * r);
    __syncthreads();

    const int4* idx4 = (const int4*)idx;
    float4*     dst4 = (float4*)(out + (size_t)p * L_);
#pragma unroll 4
    for (int r = 0; r < 8; r++) {
        int4 id = idx4[t + HT * r];
        float4 v;
        v.x = plane[id.x];
        v.y = plane[id.y];
        v.z = plane[id.z];
        v.w = plane[id.w];
        __stcs(dst4 + t + HT * r, v);
    }
}

// ---------------------------------------------------------------------------
extern "C" void kernel_launch(void* const* d_in, const int* in_sizes, int n_in,
                              void* d_out, int out_size) {
    const float* x   = (const float*)d_in[0];
    const float* w   = (const float*)d_in[1];
    const int*   idx = (const int*)d_in[2];
    float*       out = (float*)d_out;
    (void)in_sizes; (void)n_in; (void)out_size;

    cudaFuncSetAttribute(gemm_kernel,
                         cudaFuncAttributeMaxDynamicSharedMemorySize, GSMEM);
    cudaFuncSetAttribute(gather_kernel,
                         cudaFuncAttributeMaxDynamicSharedMemorySize, L_ * 4);

    dim3 ggrid(K_ / 128, 2, B_);                 // 32 x 2 x 64 = 4096 blocks
    gemm_kernel<<<ggrid, 256, GSMEM>>>(x, w);

    gather_kernel<<<B_ * COUT, HT, L_ * 4>>>(idx, out);
}

// round 12
// speedup vs baseline: 2.2526x; 1.0016x over previous
#include <cuda_runtime.h>
#include <cuda_bf16.h>
#include <cstdint>
#include <cstddef>

// Problem constants:
//   x: [B=64, Cin=64, T=1, K=4096] f32
//   w: [Cin=64, Cout=64, F=4] f32   (w[i][m], m = o*4+f, M=256)
//   idx: [L=16384] i32
//   out[b,o,l] = res[b, m=(o*4+f), k],  f=idx[l]>>12, k=idx[l]&4095
#define B_    64
#define CIN   64
#define K_    4096
#define COUT  64
#define L_    16384
#define M_    256

// 268 MB scratch: res[b][m][k]
__device__ float g_res[(size_t)B_ * M_ * K_];

// ---------------------------------------------------------------------------
// bf16 helpers
// ---------------------------------------------------------------------------
__device__ __forceinline__ void bf16_split2(float v0, float v1,
                                            uint32_t& hi, uint32_t& lo) {
    __nv_bfloat16 h0 = __float2bfloat16(v0);
    __nv_bfloat16 h1 = __float2bfloat16(v1);
    float r0 = v0 - __bfloat162float(h0);
    float r1 = v1 - __bfloat162float(h1);
    hi = (uint32_t)__bfloat16_as_ushort(h0) |
         ((uint32_t)__bfloat16_as_ushort(h1) << 16);
    lo = (uint32_t)__bfloat16_as_ushort(__float2bfloat16(r0)) |
         ((uint32_t)__bfloat16_as_ushort(__float2bfloat16(r1)) << 16);
}

// mma.sync m16n8k16 row.col bf16 -> f32  (baseline PTX, valid on sm_103)
__device__ __forceinline__ void mma_bf16(float* d, const uint32_t* a,
                                         const uint32_t* b) {
    asm volatile(
        "mma.sync.aligned.m16n8k16.row.col.f32.bf16.bf16.f32 "
        "{%0,%1,%2,%3}, {%4,%5,%6,%7}, {%8,%9}, {%0,%1,%2,%3};"
        : "+f"(d[0]), "+f"(d[1]), "+f"(d[2]), "+f"(d[3])
        : "r"(a[0]), "r"(a[1]), "r"(a[2]), "r"(a[3]), "r"(b[0]), "r"(b[1]));
}

// ---------------------------------------------------------------------------
// Kernel 1: split-bf16 HMMA GEMM  res[b,m,k] = sum_i w[i,m] * x[b,i,k]
//   3-term split: Wh*Xh + Wh*Xl + Wl*Xh  (f32 accum), rel err ~2^-16.
//   Block: 256 thr, tile M=128 x N=128, K=64 staged once. 2 CTAs/SM.
//   Warp tile m32 x n64 (4 m-warps x 2 n-warps).
//   Smem rows of 36 b32 words (32 data + 4 pad): bank = (4*row + col) % 32
//   -> fragment LDS.32 (lanes g=0..7, t=0..3) conflict-free.
// ---------------------------------------------------------------------------
#define ROWW 36
#define AH_OFF 0
#define AL_OFF (128 * ROWW)
#define BH_OFF (2 * 128 * ROWW)
#define BL_OFF (3 * 128 * ROWW)
#define GSMEM  (4 * 128 * ROWW * 4)     // 73728 B -> 2 CTAs/SM

__global__ void __launch_bounds__(256, 2)
gemm_kernel(const float* __restrict__ x, const float* __restrict__ w) {
    extern __shared__ uint32_t sm32[];

    const int t  = threadIdx.x;
    const int k0 = blockIdx.x * 128;
    const int m0 = blockIdx.y * 128;
    const int b  = blockIdx.z;

    // ---- stage: threads 0-127 -> A rows (m), threads 128-255 -> B rows (n) ----
    {
        const int r   = t & 127;
        const bool isB = t >= 128;
        const float* src;
        size_t stride;
        if (isB) { src = x + (((size_t)b * CIN) << 12) + k0 + r; stride = K_; }
        else     { src = w + m0 + r;                              stride = M_; }
        uint32_t* dh = sm32 + (isB ? BH_OFF : AH_OFF) + r * ROWW;
        uint32_t* dl = sm32 + (isB ? BL_OFF : AL_OFF) + r * ROWW;
        const int ph = (r >> 3) & 3;     // stagger: conflict-free STS
#pragma unroll 8
        for (int q = 0; q < 32; q++) {
            int ip = (q + ph) & 31;      // i-pair index
            float v0 = src[(size_t)(2 * ip)     * stride];
            float v1 = src[(size_t)(2 * ip + 1) * stride];
            uint32_t hi, lo;
            bf16_split2(v0, v1, hi, lo);
            dh[ip] = hi;
            dl[ip] = lo;
        }
    }
    __syncthreads();

    // ---- compute ----
    const int lane = t & 31;
    const int wq   = t >> 5;
    const int wm   = wq & 3;            // 0..3 : m-warp (32 rows each)
    const int wn   = wq >> 2;           // 0..1 : n-warp (64 cols each)
    const int g    = lane >> 2;
    const int tg   = lane & 3;

    float acc[2][8][4];
#pragma unroll
    for (int mt = 0; mt < 2; mt++)
#pragma unroll
        for (int j = 0; j < 8; j++)
#pragma unroll
            for (int e = 0; e < 4; e++) acc[mt][j][e] = 0.0f;

    const int aR0 = (32 * wm + g) * ROWW;        // a-row base (mt=0), +16*ROWW mt=1
    const int bR0 = (64 * wn + g) * ROWW;        // b-row base (j=0), +8*ROWW per j

#pragma unroll
    for (int ks = 0; ks < 4; ks++) {
        const int c0 = 8 * ks + tg;              // frag word col (a0/a1/b0)
        const int c4 = c0 + 4;                   // (a2/a3/b1)

        // Ah fragments (2 m-tiles)
        uint32_t ah[2][4];
#pragma unroll
        for (int mt = 0; mt < 2; mt++) {
            int rb = aR0 + AH_OFF + mt * 16 * ROWW;
            ah[mt][0] = sm32[rb + c0];
            ah[mt][1] = sm32[rb + 8 * ROWW + c0];
            ah[mt][2] = sm32[rb + c4];
            ah[mt][3] = sm32[rb + 8 * ROWW + c4];
        }
        // Bh fragments, kept for the Al pass
        uint32_t bh[8][2];
#pragma unroll
        for (int j = 0; j < 8; j++) {
            int rb = bR0 + BH_OFF + j * 8 * ROWW;
            bh[j][0] = sm32[rb + c0];
            bh[j][1] = sm32[rb + c4];
        }
        // term 1: Ah * Bh
#pragma unroll
        for (int j = 0; j < 8; j++) {
            mma_bf16(acc[0][j], ah[0], bh[j]);
            mma_bf16(acc[1][j], ah[1], bh[j]);
        }
        // term 2: Ah * Bl (streamed)
#pragma unroll
        for (int j = 0; j < 8; j++) {
            int rb = bR0 + BL_OFF + j * 8 * ROWW;
            uint32_t bl[2] = { sm32[rb + c0], sm32[rb + c4] };
            mma_bf16(acc[0][j], ah[0], bl);
            mma_bf16(acc[1][j], ah[1], bl);
        }
        // term 3: Al * Bh (reuse kept bh)
        uint32_t al[2][4];
#pragma unroll
        for (int mt = 0; mt < 2; mt++) {
            int rb = aR0 + AL_OFF + mt * 16 * ROWW;
            al[mt][0] = sm32[rb + c0];
            al[mt][1] = sm32[rb + 8 * ROWW + c0];
            al[mt][2] = sm32[rb + c4];
            al[mt][3] = sm32[rb + 8 * ROWW + c4];
        }
#pragma unroll
        for (int j = 0; j < 8; j++) {
            mma_bf16(acc[0][j], al[0], bh[j]);
            mma_bf16(acc[1][j], al[1], bh[j]);
        }
    }

    // ---- epilogue: direct STG.64, 32B sectors fully covered ----
#pragma unroll
    for (int mt = 0; mt < 2; mt++) {
        int row0 = m0 + 32 * wm + 16 * mt + g;
        float* d0 = g_res + (((size_t)b * M_ + row0) << 12) + k0 + 64 * wn + 2 * tg;
        float* d1 = d0 + ((size_t)8 << 12);
#pragma unroll
        for (int j = 0; j < 8; j++) {
            *(float2*)(d0 + 8 * j) = make_float2(acc[mt][j][0], acc[mt][j][1]);
            *(float2*)(d1 + 8 * j) = make_float2(acc[mt][j][2], acc[mt][j][3]);
        }
    }
}

// ---------------------------------------------------------------------------
// Kernel 2: per-plane gather. block = (b,o) plane (64 KB), 512 threads.
// ---------------------------------------------------------------------------
#define HT 512

__global__ void __launch_bounds__(HT, 2)
gather_kernel(const int* __restrict__ idx, float* __restrict__ out) {
    extern __shared__ float plane[];   // 16384 floats = 64 KB
    const int t = threadIdx.x;
    const int p = blockIdx.x;          // b*64 + o

    const float4* src4 = (const float4*)(g_res + (size_t)p * L_);
    float4*       pl4  = (float4*)plane;
#pragma unroll
    for (int r = 0; r < 8; r++)
        pl4[t + HT * r] = __ldcs(src4 + t + HT * r);
    __syncthreads();

    const int4* idx4 = (const int4*)idx;
    float4*     dst4 = (float4*)(out + (size_t)p * L_);
#pragma unroll 4
    for (int r = 0; r < 8; r++) {
        int4 id = idx4[t + HT * r];
        float4 v;
        v.x = plane[id.x];
        v.y = plane[id.y];
        v.z = plane[id.z];
        v.w = plane[id.w];
        __stcs(dst4 + t + HT * r, v);
    }
}

// ---------------------------------------------------------------------------
extern "C" void kernel_launch(void* const* d_in, const int* in_sizes, int n_in,
                              void* d_out, int out_size) {
    const float* x   = (const float*)d_in[0];
    const float* w   = (const float*)d_in[1];
    const int*   idx = (const int*)d_in[2];
    float*       out = (float*)d_out;
    (void)in_sizes; (void)n_in; (void)out_size;

    cudaFuncSetAttribute(gemm_kernel,
                         cudaFuncAttributeMaxDynamicSharedMemorySize, GSMEM);
    cudaFuncSetAttribute(gather_kernel,
                         cudaFuncAttributeMaxDynamicSharedMemorySize, L_ * 4);

    dim3 ggrid(K_ / 128, 2, B_);                 // 32 x 2 x 64 = 4096 blocks
    gemm_kernel<<<ggrid, 256, GSMEM>>>(x, w);

    gather_kernel<<<B_ * COUT, HT, L_ * 4>>>(idx, out);
}